// round 6
// baseline (speedup 1.0000x reference)
#include <cuda_runtime.h>
#include <cuda_fp16.h>
#include <cstdint>

#define KDIM 64
#define SDIM 512
#define TILE_M 128
#define NT 256
#define GRID 148
#define TAU 3e-4f
#define PH 72              // halves per smem row (144B = 9 x 16B -> ldmatrix conflict-free)

// smem byte offsets
#define OFF_BH    0
#define OFF_BL    73728
#define OFF_AH    147456
#define OFF_AL    165888
#define OFF_STAGE 184320
#define OFF_CN    217088
#define OFF_VN    219136
#define OFF_ZROW  219648
#define OFF_RED   220160
#define SMEM_TOTAL 220672

typedef unsigned long long ull;

__device__ float  g_cn[SDIM];
__device__ __half g_bh[SDIM * KDIM];
__device__ __half g_bl[SDIM * KDIM];
__device__ float  g_partial[GRID];
__device__ unsigned g_ticket;
__device__ int    g_flags[65536];
__device__ int    g_flagcnt;

__device__ __forceinline__ uint32_t smem_u32(const void* p) {
    uint32_t a;
    asm("{ .reg .u64 t; cvta.to.shared.u64 t, %1; cvt.u32.u64 %0, t; }" : "=r"(a) : "l"(p));
    return a;
}
__device__ __forceinline__ void cp16(char* dst, const char* src) {
    unsigned d = smem_u32(dst);
    asm volatile("cp.async.cg.shared.global [%0], [%1], 16;" :: "r"(d), "l"(src));
}
__device__ __forceinline__ void cp_commit() { asm volatile("cp.async.commit_group;"); }

__device__ __forceinline__ void ldsm4(uint32_t& r0, uint32_t& r1, uint32_t& r2, uint32_t& r3,
                                      uint32_t a) {
    asm volatile("ldmatrix.sync.aligned.m8n8.x4.shared.b16 {%0,%1,%2,%3}, [%4];"
                 : "=r"(r0), "=r"(r1), "=r"(r2), "=r"(r3) : "r"(a));
}
__device__ __forceinline__ void mma16816(float* d, const uint32_t* a,
                                         uint32_t b0, uint32_t b1) {
    asm volatile("mma.sync.aligned.m16n8k16.row.col.f32.f16.f16.f32 "
                 "{%0,%1,%2,%3}, {%4,%5,%6,%7}, {%8,%9}, {%0,%1,%2,%3};"
                 : "+f"(d[0]), "+f"(d[1]), "+f"(d[2]), "+f"(d[3])
                 : "r"(a[0]), "r"(a[1]), "r"(a[2]), "r"(a[3]), "r"(b0), "r"(b1));
}
__device__ __forceinline__ void upd(float& best, float& sec, int& idx, float v, int s) {
    if (v < best) { sec = best; best = v; idx = s; }
    else          { sec = fminf(sec, v); }
}

// ---------------------------------------------------------------------------
// Prep: codebook norms (exact R4 rounding) + fp16 hi/lo splits; reset flagcnt
// ---------------------------------------------------------------------------
__global__ void vq_prep(const float* __restrict__ cb) {
    int s = blockIdx.x * blockDim.x + threadIdx.x;
    if (s == 0) g_flagcnt = 0;
    if (s < SDIM) {
        const float4* r = (const float4*)(cb + (long)s * KDIM);
        float acc = 0.f;
        #pragma unroll
        for (int q = 0; q < KDIM / 4; q++) {
            float4 v = r[q];
            acc = fmaf(v.x, v.x, acc);
            acc = fmaf(v.y, v.y, acc);
            acc = fmaf(v.z, v.z, acc);
            acc = fmaf(v.w, v.w, acc);
        }
        g_cn[s] = acc;
        for (int k = 0; k < KDIM; k++) {
            float x = cb[s * KDIM + k];
            __half h = __float2half_rn(x);
            __half l = __float2half_rn(x - __half2float(h));
            g_bh[s * KDIM + k] = h;
            g_bl[s * KDIM + k] = l;
        }
    }
}

// ---------------------------------------------------------------------------
// Main: persistent HMMA fp16-split GEMM + approx argmin (best/second) + flags
//  - B splits (512x64 x2) resident in smem, pitched 72 halves/row
//  - A tiles of 128 vectors streamed (stage fp32 -> split to ah/al)
//  - warp w owns rows [16w,16w+16); D frags m16n8k16; cn added in epilogue
// ---------------------------------------------------------------------------
__global__ void __launch_bounds__(NT, 1)
vq_mma(const float* __restrict__ vecs, const float* __restrict__ cb,
       float* __restrict__ out, int N, int ntiles, int nctas)
{
    extern __shared__ char smb[];
    float* stage  = (float*)(smb + OFF_STAGE);
    float* cnsm   = (float*)(smb + OFF_CN);
    float* vn_s   = (float*)(smb + OFF_VN);
    int*   zrow   = (int*)(smb + OFF_ZROW);
    float* redrow = (float*)(smb + OFF_RED);

    const int tid  = threadIdx.x;
    const int lane = tid & 31;
    const int wid  = tid >> 5;

    // ---- prologue: B splits (pitched) + cn + first A stage ----
    for (int n = tid; n < SDIM * 8; n += NT) {        // 8 x 16B chunks per row
        int row = n >> 3, ch = n & 7;
        cp16(smb + OFF_BH + row * 144 + ch * 16, (const char*)g_bh + row * 128 + ch * 16);
        cp16(smb + OFF_BL + row * 144 + ch * 16, (const char*)g_bl + row * 128 + ch * 16);
    }
    for (int n = tid; n < SDIM / 4; n += NT)
        cp16(smb + OFF_CN + n * 16, (const char*)g_cn + n * 16);
    {
        const char* src = (const char*)(vecs + (long)blockIdx.x * TILE_M * KDIM);
        for (int n = tid; n < TILE_M * KDIM / 4; n += NT)
            cp16(smb + OFF_STAGE + n * 16, src + n * 16);
    }
    cp_commit();

    // per-lane fixed ldmatrix address components
    const uint32_t a_lane_off =
        ((lane & 7) + ((lane >> 3) & 1) * 8) * 144 + (lane >> 4) * 16;
    const uint32_t b_lane_off =
        ((lane & 7) + ((lane >> 4) & 1) * 8) * 144 + ((lane >> 3) & 1) * 16;
    const uint32_t ah_base = smem_u32(smb + OFF_AH) + wid * 16 * 144 + a_lane_off;
    const uint32_t al_base = smem_u32(smb + OFF_AL) + wid * 16 * 144 + a_lane_off;
    const uint32_t bh_base = smem_u32(smb + OFF_BH) + b_lane_off;
    const uint32_t bl_base = smem_u32(smb + OFF_BL) + b_lane_off;

    float csum = 0.f;
    float* out_z = out + (long)N * KDIM;

    for (int tile = blockIdx.x; tile < ntiles; tile += nctas) {
        asm volatile("cp.async.wait_group 0;");
        __syncthreads();

        // ---- split phase: ah/al = fp16 split of (-2 * a); vn ----
        #pragma unroll
        for (int e = 0; e < TILE_M * KDIM / NT; e++) {
            int idx = e * NT + tid;
            int row = idx >> 6, col = idx & 63;
            float x = -2.0f * stage[idx];
            __half h = __float2half_rn(x);
            __half l = __float2half_rn(x - __half2float(h));
            *(__half*)(smb + OFF_AH + row * 144 + col * 2) = h;
            *(__half*)(smb + OFF_AL + row * 144 + col * 2) = l;
        }
        if (tid < TILE_M) {
            const float4* r = (const float4*)(stage + tid * KDIM);
            float acc = 0.f;
            #pragma unroll
            for (int q = 0; q < KDIM / 4; q++) {
                float4 v = r[q];
                acc = fmaf(v.x, v.x, acc);
                acc = fmaf(v.y, v.y, acc);
                acc = fmaf(v.z, v.z, acc);
                acc = fmaf(v.w, v.w, acc);
            }
            vn_s[tid] = acc;
        }
        __syncthreads();

        // ---- prefetch next A tile ----
        if (tile + nctas < ntiles) {
            const char* src = (const char*)(vecs + (long)(tile + nctas) * TILE_M * KDIM);
            for (int n = tid; n < TILE_M * KDIM / 4; n += NT)
                cp16(smb + OFF_STAGE + n * 16, src + n * 16);
        }
        cp_commit();

        // ---- MMA + per-lane best/second over all 512 codewords ----
        float bestL = 3.4e38f, secL = 3.4e38f, bestH = 3.4e38f, secH = 3.4e38f;
        int idxL = 0, idxH = 0;

        #pragma unroll 1
        for (int c = 0; c < 4; c++) {
            float acc[16][4];
            #pragma unroll
            for (int nt = 0; nt < 16; nt++)
                #pragma unroll
                for (int q = 0; q < 4; q++) acc[nt][q] = 0.f;

            #pragma unroll
            for (int kk = 0; kk < 4; kk++) {
                uint32_t ahf[4], alf[4];
                ldsm4(ahf[0], ahf[1], ahf[2], ahf[3], ah_base + kk * 32);
                ldsm4(alf[0], alf[1], alf[2], alf[3], al_base + kk * 32);
                #pragma unroll
                for (int p = 0; p < 8; p++) {
                    uint32_t noff = (uint32_t)(c * 128 + p * 16) * 144 + kk * 32;
                    uint32_t h0, h1, h2, h3, l0, l1, l2, l3;
                    ldsm4(h0, h1, h2, h3, bh_base + noff);
                    ldsm4(l0, l1, l2, l3, bl_base + noff);
                    mma16816(acc[2 * p],     ahf, h0, h1);
                    mma16816(acc[2 * p + 1], ahf, h2, h3);
                    mma16816(acc[2 * p],     ahf, l0, l1);
                    mma16816(acc[2 * p + 1], ahf, l2, l3);
                    mma16816(acc[2 * p],     alf, h0, h1);
                    mma16816(acc[2 * p + 1], alf, h2, h3);
                }
            }
            // chunk epilogue: add cn, track best/second
            #pragma unroll
            for (int nt = 0; nt < 16; nt++) {
                int c0 = c * 128 + nt * 8 + (lane & 3) * 2;
                float2 cn2 = *(const float2*)&cnsm[c0];
                upd(bestL, secL, idxL, acc[nt][0] + cn2.x, c0);
                upd(bestL, secL, idxL, acc[nt][1] + cn2.y, c0 + 1);
                upd(bestH, secH, idxH, acc[nt][2] + cn2.x, c0);
                upd(bestH, secH, idxH, acc[nt][3] + cn2.y, c0 + 1);
            }
        }

        // ---- quad reduce (lanes sharing the same row) ----
        #pragma unroll
        for (int m = 1; m <= 2; m <<= 1) {
            float ob = __shfl_xor_sync(0xffffffffu, bestL, m);
            float os = __shfl_xor_sync(0xffffffffu, secL, m);
            int   oi = __shfl_xor_sync(0xffffffffu, idxL, m);
            if (ob < bestL) { secL = fminf(bestL, os); bestL = ob; idxL = oi; }
            else            { secL = fminf(secL, ob); }
            ob = __shfl_xor_sync(0xffffffffu, bestH, m);
            os = __shfl_xor_sync(0xffffffffu, secH, m);
            oi = __shfl_xor_sync(0xffffffffu, idxH, m);
            if (ob < bestH) { secH = fminf(bestH, os); bestH = ob; idxH = oi; }
            else            { secH = fminf(secH, ob); }
        }

        const long i0 = (long)tile * TILE_M;
        if ((lane & 3) == 0) {
            int row = wid * 16 + (lane >> 2);
            zrow[row] = idxL;
            out_z[i0 + row] = (float)idxL;
            redrow[row] = fmaxf(vn_s[row] + bestL, 0.0f);
            if (secL - bestL <= TAU) { int p = atomicAdd(&g_flagcnt, 1); g_flags[p] = (int)(i0 + row); }
            row += 8;
            zrow[row] = idxH;
            out_z[i0 + row] = (float)idxH;
            redrow[row] = fmaxf(vn_s[row] + bestH, 0.0f);
            if (secH - bestH <= TAU) { int p = atomicAdd(&g_flagcnt, 1); g_flags[p] = (int)(i0 + row); }
        }
        __syncthreads();

        // ---- gather vecs_hat = codebook[z]; loss partial ----
        for (int n = tid; n < TILE_M * (KDIM / 4); n += NT) {
            int row = n >> 4, q = n & 15;
            float4 v = __ldg((const float4*)(cb + (long)zrow[row] * KDIM) + q);
            *(float4*)(out + (i0 + row) * KDIM + q * 4) = v;
        }
        if (tid == 0) {
            float s = 0.f;
            #pragma unroll 8
            for (int x = 0; x < TILE_M; x++) s += redrow[x];
            csum += s;
        }
    }

    // ---- in-kernel deterministic loss reduction ----
    if (tid == 0) {
        g_partial[blockIdx.x] = csum;
        __threadfence();
        unsigned t = atomicAdd(&g_ticket, 1u);
        if (t == (unsigned)(nctas - 1)) {
            double tot = 0.0;
            for (int i = 0; i < nctas; i++)
                tot += (double)(*(volatile float*)&g_partial[i]);
            float mean = (float)(tot / (double)N);
            long base = (long)N * KDIM + N;
            out[base]     = mean;   // l_commit
            out[base + 1] = mean;   // l_codebook (identical forward value)
            g_ticket = 0;
        }
    }
}

// ---------------------------------------------------------------------------
// Cleanup: exact rescan (bit-identical R4 rounding) for flagged vectors
// ---------------------------------------------------------------------------
__global__ void __launch_bounds__(128, 8)
vq_cleanup(const float* __restrict__ vecs, const float* __restrict__ cb,
           float* __restrict__ out, int N)
{
    const int lane = threadIdx.x & 31;
    const int gw = (blockIdx.x * blockDim.x + threadIdx.x) >> 5;
    const int nw = (gridDim.x * blockDim.x) >> 5;
    const int cnt = g_flagcnt;
    float* out_z = out + (long)N * KDIM;

    for (int w = gw; w < cnt; w += nw) {
        const int i = g_flags[w];
        const float* v = vecs + (long)i * KDIM;
        float vn = 0.f;
        #pragma unroll
        for (int q = 0; q < KDIM / 4; q++) {
            float4 t = __ldg((const float4*)v + q);
            vn = fmaf(t.x, t.x, vn);
            vn = fmaf(t.y, t.y, vn);
            vn = fmaf(t.z, t.z, vn);
            vn = fmaf(t.w, t.w, vn);
        }
        ull bk = ~0ull;
        for (int jj = 0; jj < 16; jj++) {
            int s = lane * 16 + jj;
            const float* c = cb + (long)s * KDIM;
            float ae = 0.f, ao = 0.f;   // even/odd fma chains
            #pragma unroll
            for (int kp = 0; kp < KDIM / 2; kp++) {
                ae = fmaf(v[2 * kp],     c[2 * kp],     ae);
                ao = fmaf(v[2 * kp + 1], c[2 * kp + 1], ao);
            }
            float dot = __fadd_rn(ae, ao);
            float d = __fadd_rn(__fmaf_rn(-2.0f, dot, vn), g_cn[s]);
            ull key = ((ull)__float_as_uint(d) << 32) | (unsigned)s;
            bk = key < bk ? key : bk;
        }
        #pragma unroll
        for (int o = 16; o > 0; o >>= 1) {
            ull other = __shfl_xor_sync(0xffffffffu, bk, o);
            bk = other < bk ? other : bk;
        }
        int z = (int)(bk & 0xffffffffull);
        if (lane == 0) out_z[i] = (float)z;
        out[(long)i * KDIM + lane]      = __ldg(&cb[(long)z * KDIM + lane]);
        out[(long)i * KDIM + lane + 32] = __ldg(&cb[(long)z * KDIM + lane + 32]);
    }
}

extern "C" void kernel_launch(void* const* d_in, const int* in_sizes, int n_in,
                              void* d_out, int out_size) {
    const float* vecs = (const float*)d_in[0];
    const float* cb   = (const float*)d_in[1];
    float* out = (float*)d_out;

    int N = in_sizes[0] / KDIM;          // 65536
    int ntiles = N / TILE_M;             // 512
    int nctas = ntiles < GRID ? ntiles : GRID;

    cudaFuncSetAttribute(vq_mma, cudaFuncAttributeMaxDynamicSharedMemorySize, SMEM_TOTAL);

    vq_prep<<<2, 256>>>(cb);
    vq_mma<<<nctas, NT, SMEM_TOTAL>>>(vecs, cb, out, N, ntiles, nctas);
    vq_cleanup<<<256, 128>>>(vecs, cb, out, N);
}

// round 7
// speedup vs baseline: 1.2600x; 1.2600x over previous
#include <cuda_runtime.h>
#include <cuda_fp16.h>
#include <cstdint>

#define KDIM 64
#define SDIM 512
#define TILE_M 128
#define NT 256
#define GRID 148
#define TAU 3e-4f

// smem byte offsets (rows pitched 144B = 9 x 16B -> ldmatrix conflict-free)
#define OFF_BH    0
#define OFF_BL    73728
#define OFF_AH    147456
#define OFF_AL    165888
#define OFF_STAGE 184320
#define OFF_CN    217088
#define OFF_VN    219136
#define OFF_ZROW  219648
#define OFF_RED   220160
#define OFF_FLG   220672
#define OFF_FCNT  222720
#define SMEM_TOTAL 222752

typedef unsigned long long ull;

__device__ float    g_partial[GRID];
__device__ unsigned g_ticket;

__device__ __forceinline__ uint32_t smem_u32(const void* p) {
    uint32_t a;
    asm("{ .reg .u64 t; cvta.to.shared.u64 t, %1; cvt.u32.u64 %0, t; }" : "=r"(a) : "l"(p));
    return a;
}
__device__ __forceinline__ void cp16(char* dst, const char* src) {
    unsigned d = smem_u32(dst);
    asm volatile("cp.async.cg.shared.global [%0], [%1], 16;" :: "r"(d), "l"(src));
}
__device__ __forceinline__ void cp_commit() { asm volatile("cp.async.commit_group;"); }

__device__ __forceinline__ void ldsm4(uint32_t& r0, uint32_t& r1, uint32_t& r2, uint32_t& r3,
                                      uint32_t a) {
    asm volatile("ldmatrix.sync.aligned.m8n8.x4.shared.b16 {%0,%1,%2,%3}, [%4];"
                 : "=r"(r0), "=r"(r1), "=r"(r2), "=r"(r3) : "r"(a));
}
__device__ __forceinline__ void mma16816(float* d, const uint32_t* a,
                                         uint32_t b0, uint32_t b1) {
    asm volatile("mma.sync.aligned.m16n8k16.row.col.f32.f16.f16.f32 "
                 "{%0,%1,%2,%3}, {%4,%5,%6,%7}, {%8,%9}, {%0,%1,%2,%3};"
                 : "+f"(d[0]), "+f"(d[1]), "+f"(d[2]), "+f"(d[3])
                 : "r"(a[0]), "r"(a[1]), "r"(a[2]), "r"(a[3]), "r"(b0), "r"(b1));
}
struct BS { float best, sec; int idx; };
__device__ __forceinline__ void upd(BS& c, float v, int s) {
    if (v < c.best) { c.sec = c.best; c.best = v; c.idx = s; }
    else            { c.sec = fminf(c.sec, v); }
}
__device__ __forceinline__ void mergeBS(BS& a, const BS& b) {
    if (b.best < a.best) { a.sec = fminf(a.best, b.sec); a.best = b.best; a.idx = b.idx; }
    else                 { a.sec = fminf(a.sec, b.best); }
}

// ---------------------------------------------------------------------------
// Single persistent kernel: B-split + HMMA fp16-3-split GEMM + approx argmin
// with best/second flagging + inline exact cleanup + in-kernel loss reduction
// ---------------------------------------------------------------------------
__global__ void __launch_bounds__(NT, 1)
vq_all(const float* __restrict__ vecs, const float* __restrict__ cb,
       float* __restrict__ out, int N, int ntiles, int nctas)
{
    extern __shared__ char smb[];
    float* stage  = (float*)(smb + OFF_STAGE);
    float* cnsm   = (float*)(smb + OFF_CN);
    float* vn_s   = (float*)(smb + OFF_VN);
    int*   zrow   = (int*)(smb + OFF_ZROW);
    float* redrow = (float*)(smb + OFF_RED);
    int*   flg    = (int*)(smb + OFF_FLG);
    int*   fcnt   = (int*)(smb + OFF_FCNT);

    const int tid  = threadIdx.x;
    const int lane = tid & 31;
    const int wid  = tid >> 5;

    if (tid == 0) fcnt[0] = 0;

    // ---- first A tile via cp.async (overlaps the B split below) ----
    {
        const char* src = (const char*)(vecs + (long)blockIdx.x * TILE_M * KDIM);
        for (int n = tid; n < TILE_M * KDIM / 4; n += NT)
            cp16(smb + OFF_STAGE + n * 16, src + n * 16);
    }
    cp_commit();

    // ---- B split: cb (L2-resident) -> fp16 hi/lo in smem, pitched 144B ----
    for (int n = tid; n < SDIM * (KDIM / 4); n += NT) {
        int row = n >> 4, q = n & 15;
        float4 v = __ldg((const float4*)(cb + (long)row * KDIM) + q);
        __half2 h01 = __floats2half2_rn(v.x, v.y);
        __half2 h23 = __floats2half2_rn(v.z, v.w);
        float2 hf01 = __half22float2(h01);
        float2 hf23 = __half22float2(h23);
        __half2 l01 = __floats2half2_rn(v.x - hf01.x, v.y - hf01.y);
        __half2 l23 = __floats2half2_rn(v.z - hf23.x, v.w - hf23.y);
        uint2 hp, lp;
        hp.x = *(uint32_t*)&h01; hp.y = *(uint32_t*)&h23;
        lp.x = *(uint32_t*)&l01; lp.y = *(uint32_t*)&l23;
        *(uint2*)(smb + OFF_BH + row * 144 + q * 8) = hp;
        *(uint2*)(smb + OFF_BL + row * 144 + q * 8) = lp;
    }
    // ---- codebook norms, exact fmaf chain (reference rounding) ----
    #pragma unroll
    for (int r = 0; r < SDIM / NT; r++) {
        int s = r * NT + tid;
        const float4* row = (const float4*)(cb + (long)s * KDIM);
        float acc = 0.f;
        #pragma unroll
        for (int q = 0; q < KDIM / 4; q++) {
            float4 v = __ldg(row + q);
            acc = fmaf(v.x, v.x, acc);
            acc = fmaf(v.y, v.y, acc);
            acc = fmaf(v.z, v.z, acc);
            acc = fmaf(v.w, v.w, acc);
        }
        cnsm[s] = acc;
    }

    // per-lane fixed ldmatrix address components (verified layout from R6)
    const uint32_t a_lane_off =
        ((lane & 7) + ((lane >> 3) & 1) * 8) * 144 + (lane >> 4) * 16;
    const uint32_t b_lane_off =
        ((lane & 7) + ((lane >> 4) & 1) * 8) * 144 + ((lane >> 3) & 1) * 16;
    const uint32_t ah_base = smem_u32(smb + OFF_AH) + wid * 16 * 144 + a_lane_off;
    const uint32_t al_base = smem_u32(smb + OFF_AL) + wid * 16 * 144 + a_lane_off;
    const uint32_t bh_base = smem_u32(smb + OFF_BH) + b_lane_off;
    const uint32_t bl_base = smem_u32(smb + OFF_BL) + b_lane_off;

    float csum = 0.f;
    float* out_z = out + (long)N * KDIM;

    for (int tile = blockIdx.x; tile < ntiles; tile += nctas) {
        asm volatile("cp.async.wait_group 0;");
        __syncthreads();

        // ---- A split: ah/al = fp16 split of (-2 * a), half2-vectorized ----
        #pragma unroll
        for (int e = 0; e < TILE_M * KDIM / (2 * NT); e++) {
            int p = e * NT + tid;                  // pair index
            int row = p >> 5, c2 = p & 31;
            float2 x = *(const float2*)(stage + row * KDIM + c2 * 2);
            x.x *= -2.0f; x.y *= -2.0f;
            __half2 h = __floats2half2_rn(x.x, x.y);
            float2 hf = __half22float2(h);
            __half2 l = __floats2half2_rn(x.x - hf.x, x.y - hf.y);
            *(uint32_t*)(smb + OFF_AH + row * 144 + c2 * 4) = *(uint32_t*)&h;
            *(uint32_t*)(smb + OFF_AL + row * 144 + c2 * 4) = *(uint32_t*)&l;
        }
        if (tid < TILE_M) {
            const float4* r = (const float4*)(stage + tid * KDIM);
            float acc = 0.f;
            #pragma unroll
            for (int q = 0; q < KDIM / 4; q++) {
                float4 v = r[q];
                acc = fmaf(v.x, v.x, acc);
                acc = fmaf(v.y, v.y, acc);
                acc = fmaf(v.z, v.z, acc);
                acc = fmaf(v.w, v.w, acc);
            }
            vn_s[tid] = acc;
        }
        __syncthreads();

        // ---- prefetch next A tile ----
        if (tile + nctas < ntiles) {
            const char* src = (const char*)(vecs + (long)(tile + nctas) * TILE_M * KDIM);
            for (int n = tid; n < TILE_M * KDIM / 4; n += NT)
                cp16(smb + OFF_STAGE + n * 16, src + n * 16);
        }
        cp_commit();

        // ---- MMA: 3 split terms, per-lane best/second (4 interleaved chains) ----
        BS cL0 = {3.4e38f, 3.4e38f, 0}, cL1 = cL0, cH0 = cL0, cH1 = cL0;

        #pragma unroll 1
        for (int c = 0; c < 4; c++) {
            float acc[16][4];
            #pragma unroll
            for (int nt = 0; nt < 16; nt++)
                #pragma unroll
                for (int q = 0; q < 4; q++) acc[nt][q] = 0.f;

            #pragma unroll
            for (int kk = 0; kk < 4; kk++) {
                uint32_t ahf[4], alf[4];
                ldsm4(ahf[0], ahf[1], ahf[2], ahf[3], ah_base + kk * 32);
                ldsm4(alf[0], alf[1], alf[2], alf[3], al_base + kk * 32);
                #pragma unroll
                for (int p = 0; p < 8; p++) {
                    uint32_t noff = (uint32_t)(c * 128 + p * 16) * 144 + kk * 32;
                    uint32_t h0, h1, h2, h3, l0, l1, l2, l3;
                    ldsm4(h0, h1, h2, h3, bh_base + noff);
                    ldsm4(l0, l1, l2, l3, bl_base + noff);
                    mma16816(acc[2 * p],     ahf, h0, h1);
                    mma16816(acc[2 * p + 1], ahf, h2, h3);
                    mma16816(acc[2 * p],     ahf, l0, l1);
                    mma16816(acc[2 * p + 1], ahf, l2, l3);
                    mma16816(acc[2 * p],     alf, h0, h1);
                    mma16816(acc[2 * p + 1], alf, h2, h3);
                }
            }
            // chunk epilogue: add cn, 4 independent chains (evens/odds of nt)
            #pragma unroll
            for (int nt = 0; nt < 16; nt += 2) {
                int c0 = c * 128 + nt * 8 + (lane & 3) * 2;
                float2 cn2 = *(const float2*)&cnsm[c0];
                upd(cL0, acc[nt][0] + cn2.x, c0);
                upd(cL0, acc[nt][1] + cn2.y, c0 + 1);
                upd(cH0, acc[nt][2] + cn2.x, c0);
                upd(cH0, acc[nt][3] + cn2.y, c0 + 1);
                int c1 = c0 + 8;
                float2 cn2b = *(const float2*)&cnsm[c1];
                upd(cL1, acc[nt + 1][0] + cn2b.x, c1);
                upd(cL1, acc[nt + 1][1] + cn2b.y, c1 + 1);
                upd(cH1, acc[nt + 1][2] + cn2b.x, c1);
                upd(cH1, acc[nt + 1][3] + cn2b.y, c1 + 1);
            }
        }
        mergeBS(cL0, cL1);
        mergeBS(cH0, cH1);

        // ---- quad reduce (lanes sharing the same row) ----
        #pragma unroll
        for (int m = 1; m <= 2; m <<= 1) {
            BS o;
            o.best = __shfl_xor_sync(0xffffffffu, cL0.best, m);
            o.sec  = __shfl_xor_sync(0xffffffffu, cL0.sec, m);
            o.idx  = __shfl_xor_sync(0xffffffffu, cL0.idx, m);
            mergeBS(cL0, o);
            o.best = __shfl_xor_sync(0xffffffffu, cH0.best, m);
            o.sec  = __shfl_xor_sync(0xffffffffu, cH0.sec, m);
            o.idx  = __shfl_xor_sync(0xffffffffu, cH0.idx, m);
            mergeBS(cH0, o);
        }

        const long i0 = (long)tile * TILE_M;
        if ((lane & 3) == 0) {
            int row = wid * 16 + (lane >> 2);
            zrow[row] = cL0.idx;
            out_z[i0 + row] = (float)cL0.idx;
            redrow[row] = fmaxf(vn_s[row] + cL0.best, 0.0f);
            if (cL0.sec - cL0.best <= TAU) { int p = atomicAdd_block(fcnt, 1); flg[p] = (int)(i0 + row); }
            row += 8;
            zrow[row] = cH0.idx;
            out_z[i0 + row] = (float)cH0.idx;
            redrow[row] = fmaxf(vn_s[row] + cH0.best, 0.0f);
            if (cH0.sec - cH0.best <= TAU) { int p = atomicAdd_block(fcnt, 1); flg[p] = (int)(i0 + row); }
        }
        __syncthreads();

        // ---- gather vecs_hat = codebook[z]; loss partial ----
        for (int n = tid; n < TILE_M * (KDIM / 4); n += NT) {
            int row = n >> 4, q = n & 15;
            float4 v = __ldg((const float4*)(cb + (long)zrow[row] * KDIM) + q);
            *(float4*)(out + (i0 + row) * KDIM + q * 4) = v;
        }
        if (tid == 0) {
            float s = 0.f;
            #pragma unroll 8
            for (int x = 0; x < TILE_M; x++) s += redrow[x];
            csum += s;
        }
        __syncthreads();
    }

    // ---- inline exact cleanup (bit-identical reference rounding) ----
    __syncthreads();
    {
        const int cnt = fcnt[0];
        for (int f = wid; f < cnt; f += NT / 32) {
            const int i = flg[f];
            const float* v = vecs + (long)i * KDIM;
            float vn = 0.f;
            #pragma unroll
            for (int q = 0; q < KDIM / 4; q++) {
                float4 t = __ldg((const float4*)v + q);
                vn = fmaf(t.x, t.x, vn);
                vn = fmaf(t.y, t.y, vn);
                vn = fmaf(t.z, t.z, vn);
                vn = fmaf(t.w, t.w, vn);
            }
            ull bk = ~0ull;
            for (int jj = 0; jj < 16; jj++) {
                int s = lane * 16 + jj;
                const float* c = cb + (long)s * KDIM;
                float ae = 0.f, ao = 0.f;   // even/odd fma chains
                #pragma unroll
                for (int kp = 0; kp < KDIM / 2; kp++) {
                    ae = fmaf(v[2 * kp],     c[2 * kp],     ae);
                    ao = fmaf(v[2 * kp + 1], c[2 * kp + 1], ao);
                }
                float dot = __fadd_rn(ae, ao);
                float d = __fadd_rn(__fmaf_rn(-2.0f, dot, vn), cnsm[s]);
                ull key = ((ull)__float_as_uint(d) << 32) | (unsigned)s;
                bk = key < bk ? key : bk;
            }
            #pragma unroll
            for (int o = 16; o > 0; o >>= 1) {
                ull other = __shfl_xor_sync(0xffffffffu, bk, o);
                bk = other < bk ? other : bk;
            }
            int z = (int)(bk & 0xffffffffull);
            if (lane == 0) out_z[i] = (float)z;
            out[(long)i * KDIM + lane]      = __ldg(&cb[(long)z * KDIM + lane]);
            out[(long)i * KDIM + lane + 32] = __ldg(&cb[(long)z * KDIM + lane + 32]);
        }
    }

    // ---- in-kernel deterministic loss reduction ----
    if (tid == 0) {
        g_partial[blockIdx.x] = csum;
        __threadfence();
        unsigned t = atomicAdd(&g_ticket, 1u);
        if (t == (unsigned)(nctas - 1)) {
            double tot = 0.0;
            for (int i = 0; i < nctas; i++)
                tot += (double)(*(volatile float*)&g_partial[i]);
            float mean = (float)(tot / (double)N);
            long base = (long)N * KDIM + N;
            out[base]     = mean;   // l_commit
            out[base + 1] = mean;   // l_codebook (identical forward value)
            g_ticket = 0;
        }
    }
}

extern "C" void kernel_launch(void* const* d_in, const int* in_sizes, int n_in,
                              void* d_out, int out_size) {
    const float* vecs = (const float*)d_in[0];
    const float* cb   = (const float*)d_in[1];
    float* out = (float*)d_out;

    int N = in_sizes[0] / KDIM;          // 65536
    int ntiles = N / TILE_M;             // 512
    int nctas = ntiles < GRID ? ntiles : GRID;

    cudaFuncSetAttribute(vq_all, cudaFuncAttributeMaxDynamicSharedMemorySize, SMEM_TOTAL);

    vq_all<<<nctas, NT, SMEM_TOTAL>>>(vecs, cb, out, N, ntiles, nctas);
}

// round 8
// speedup vs baseline: 1.2736x; 1.0108x over previous
#include <cuda_runtime.h>
#include <cuda_fp16.h>
#include <cstdint>

#define KDIM 64
#define SDIM 512
#define TILE_M 128
#define NT 256
#define NW 8
#define GRID 148
#define TAU 3e-4f
#define FLGMAX 1024

// smem byte offsets
#define OFF_AH   0          // 128 * 144
#define OFF_AL   18432
#define OFF_STG  36864      // 2 * 32768 (double-buffered A stage, fp32)
#define OFF_CN   102400     // 512 * 4
#define OFF_VN   104448     // 128 * 4
#define OFF_KEY  104960     // 8 * 128 * 8  (u64 keys, [warp][row])
#define OFF_SEC  113152     // 8 * 128 * 4
#define OFF_ZR   117248     // 128 * 4
#define OFF_RED  117760     // 128 * 4
#define OFF_FLG  118272     // FLGMAX * 4
#define OFF_CTL  122368     // fcnt, tnext
#define SMEM_TOTAL 122400

typedef unsigned long long ull;

__device__ float    g_tilesum[1024];
__device__ unsigned g_ticket;
__device__ unsigned g_next = GRID;   // reset to nctas by last CTA each launch

__device__ __forceinline__ uint32_t smem_u32(const void* p) {
    uint32_t a;
    asm("{ .reg .u64 t; cvta.to.shared.u64 t, %1; cvt.u32.u64 %0, t; }" : "=r"(a) : "l"(p));
    return a;
}
__device__ __forceinline__ void cp16(char* dst, const char* src) {
    unsigned d = smem_u32(dst);
    asm volatile("cp.async.cg.shared.global [%0], [%1], 16;" :: "r"(d), "l"(src));
}
__device__ __forceinline__ void cp_commit() { asm volatile("cp.async.commit_group;"); }

__device__ __forceinline__ void ldsm4(uint32_t& r0, uint32_t& r1, uint32_t& r2, uint32_t& r3,
                                      uint32_t a) {
    asm volatile("ldmatrix.sync.aligned.m8n8.x4.shared.b16 {%0,%1,%2,%3}, [%4];"
                 : "=r"(r0), "=r"(r1), "=r"(r2), "=r"(r3) : "r"(a));
}
__device__ __forceinline__ void mma16816(float* d, const uint32_t* a,
                                         uint32_t b0, uint32_t b1) {
    asm volatile("mma.sync.aligned.m16n8k16.row.col.f32.f16.f16.f32 "
                 "{%0,%1,%2,%3}, {%4,%5,%6,%7}, {%8,%9}, {%0,%1,%2,%3};"
                 : "+f"(d[0]), "+f"(d[1]), "+f"(d[2]), "+f"(d[3])
                 : "r"(a[0]), "r"(a[1]), "r"(a[2]), "r"(a[3]), "r"(b0), "r"(b1));
}
struct BS { float best, sec; int idx; };
__device__ __forceinline__ void upd(BS& c, float v, int s) {
    if (v < c.best) { c.sec = c.best; c.best = v; c.idx = s; }
    else            { c.sec = fminf(c.sec, v); }
}
__device__ __forceinline__ void mergeBS(BS& a, const BS& b) {
    if (b.best < a.best) { a.sec = fminf(a.best, b.sec); a.best = b.best; a.idx = b.idx; }
    else                 { a.sec = fminf(a.sec, b.best); }
}
// monotone float<->uint encoding (scores can be negative: d excludes ||v||^2)
__device__ __forceinline__ unsigned fenc(float f) {
    unsigned b = __float_as_uint(f);
    return b ^ ((unsigned)((int)b >> 31) | 0x80000000u);
}
__device__ __forceinline__ float fdec(unsigned e) {
    unsigned b = e ^ ((unsigned)((int)(~e) >> 31) | 0x80000000u);
    return __uint_as_float(b);
}
__device__ __forceinline__ void split16(float x, float y, uint32_t& h, uint32_t& l) {
    __half2 h2 = __floats2half2_rn(x, y);
    float2 hf = __half22float2(h2);
    __half2 l2 = __floats2half2_rn(x - hf.x, y - hf.y);
    h = *(uint32_t*)&h2; l = *(uint32_t*)&l2;
}

// ---------------------------------------------------------------------------
// Single persistent kernel, B fragments register-resident, dynamic tile steal.
// ---------------------------------------------------------------------------
__global__ void __launch_bounds__(NT, 1)
vq_all(const float* __restrict__ vecs, const float* __restrict__ cb,
       float* __restrict__ out, int N, int ntiles, int nctas)
{
    extern __shared__ char smb[];
    float* cnsm   = (float*)(smb + OFF_CN);
    float* vn_s   = (float*)(smb + OFF_VN);
    ull*   keyb   = (ull*)(smb + OFF_KEY);
    float* secb   = (float*)(smb + OFF_SEC);
    int*   zrow   = (int*)(smb + OFF_ZR);
    float* redrow = (float*)(smb + OFF_RED);
    int*   flg    = (int*)(smb + OFF_FLG);
    int*   fcnt   = (int*)(smb + OFF_CTL);
    int*   tnx    = (int*)(smb + OFF_CTL + 4);

    const int tid  = threadIdx.x;
    const int lane = tid & 31;
    const int wid  = tid >> 5;
    const int col2 = (lane & 3) * 2;

    if (tid == 0) fcnt[0] = 0;

    // ---- stage first A tile ----
    {
        const char* src = (const char*)(vecs + (long)blockIdx.x * TILE_M * KDIM);
        for (int n = tid; n < TILE_M * KDIM / 4; n += NT)
            cp16(smb + OFF_STG + n * 16, src + n * 16);
    }
    cp_commit();

    // ---- B fragments -> registers (hi/lo fp16 split), once per CTA ----
    // b0 = {B[k][n], B[k+1][n]}, b1 = k+8; n = wid*64 + nb*8 + (lane>>2)
    uint32_t bh[8][4][2], bl[8][4][2];
    #pragma unroll
    for (int nb = 0; nb < 8; nb++) {
        const float* bp = cb + (long)(wid * 64 + nb * 8 + (lane >> 2)) * KDIM + col2;
        #pragma unroll
        for (int kk = 0; kk < 4; kk++) {
            float2 p0 = *(const float2*)(bp + kk * 16);
            float2 p1 = *(const float2*)(bp + kk * 16 + 8);
            split16(p0.x, p0.y, bh[nb][kk][0], bl[nb][kk][0]);
            split16(p1.x, p1.y, bh[nb][kk][1], bl[nb][kk][1]);
        }
    }

    // ---- codebook norms (exact reference rounding) ----
    #pragma unroll
    for (int r = 0; r < SDIM / NT; r++) {
        int s = r * NT + tid;
        const float4* row = (const float4*)(cb + (long)s * KDIM);
        float acc = 0.f;
        #pragma unroll
        for (int q = 0; q < KDIM / 4; q++) {
            float4 v = __ldg(row + q);
            acc = fmaf(v.x, v.x, acc);
            acc = fmaf(v.y, v.y, acc);
            acc = fmaf(v.z, v.z, acc);
            acc = fmaf(v.w, v.w, acc);
        }
        cnsm[s] = acc;
    }
    __syncthreads();

    const uint32_t a_lane_off =
        ((lane & 7) + ((lane >> 3) & 1) * 8) * 144 + (lane >> 4) * 16;
    const uint32_t ah0 = smem_u32(smb + OFF_AH) + a_lane_off;
    const uint32_t al0 = smem_u32(smb + OFF_AL) + a_lane_off;

    float* out_z = out + (long)N * KDIM;
    int tile = blockIdx.x;
    int buf = 0;

    while (tile < ntiles) {
        if (tid == 0) tnx[0] = (int)atomicAdd(&g_next, 1u);
        asm volatile("cp.async.wait_group 0;");
        __syncthreads();

        // ---- A split: fp16 hi/lo of (-2 * a) into pitched smem; vn ----
        const float* stg = (const float*)(smb + OFF_STG) + buf * (TILE_M * KDIM);
        #pragma unroll
        for (int e = 0; e < TILE_M * KDIM / (2 * NT); e++) {
            int p = e * NT + tid;
            int row = p >> 5, c2 = p & 31;
            float2 x = *(const float2*)(stg + row * KDIM + c2 * 2);
            uint32_t h, l;
            split16(-2.0f * x.x, -2.0f * x.y, h, l);
            *(uint32_t*)(smb + OFF_AH + row * 144 + c2 * 4) = h;
            *(uint32_t*)(smb + OFF_AL + row * 144 + c2 * 4) = l;
        }
        if (tid < TILE_M) {
            const float4* r = (const float4*)(stg + tid * KDIM);
            float acc = 0.f;
            #pragma unroll
            for (int q = 0; q < KDIM / 4; q++) {
                float4 v = r[q];
                acc = fmaf(v.x, v.x, acc);
                acc = fmaf(v.y, v.y, acc);
                acc = fmaf(v.z, v.z, acc);
                acc = fmaf(v.w, v.w, acc);
            }
            vn_s[tid] = acc;
        }
        __syncthreads();

        const int tnext = tnx[0];
        if (tnext < ntiles) {
            const char* src = (const char*)(vecs + (long)tnext * TILE_M * KDIM);
            char* dst = smb + OFF_STG + (buf ^ 1) * 32768;
            for (int n = tid; n < TILE_M * KDIM / 4; n += NT)
                cp16(dst + n * 16, src + n * 16);
        }
        cp_commit();

        // ---- 8 m-blocks: ldsm A, 3-term MMA vs register B, best/second ----
        #pragma unroll 1
        for (int mb = 0; mb < 8; mb++) {
            float acc[8][4];
            #pragma unroll
            for (int nb = 0; nb < 8; nb++)
                #pragma unroll
                for (int q = 0; q < 4; q++) acc[nb][q] = 0.f;

            #pragma unroll
            for (int kk = 0; kk < 4; kk++) {
                uint32_t ahf[4], alf[4];
                ldsm4(ahf[0], ahf[1], ahf[2], ahf[3], ah0 + mb * 2304 + kk * 32);
                ldsm4(alf[0], alf[1], alf[2], alf[3], al0 + mb * 2304 + kk * 32);
                #pragma unroll
                for (int nb = 0; nb < 8; nb++) {
                    mma16816(acc[nb], ahf, bh[nb][kk][0], bh[nb][kk][1]);
                    mma16816(acc[nb], ahf, bl[nb][kk][0], bl[nb][kk][1]);
                    mma16816(acc[nb], alf, bh[nb][kk][0], bh[nb][kk][1]);
                }
            }

            BS cL = {3.4e38f, 3.4e38f, 0}, cH = cL;
            #pragma unroll
            for (int nb = 0; nb < 8; nb++) {
                int s0 = wid * 64 + nb * 8 + col2;
                float2 cn2 = *(const float2*)(cnsm + s0);
                upd(cL, acc[nb][0] + cn2.x, s0);
                upd(cL, acc[nb][1] + cn2.y, s0 + 1);
                upd(cH, acc[nb][2] + cn2.x, s0);
                upd(cH, acc[nb][3] + cn2.y, s0 + 1);
            }
            #pragma unroll
            for (int m = 1; m <= 2; m <<= 1) {
                BS o;
                o.best = __shfl_xor_sync(0xffffffffu, cL.best, m);
                o.sec  = __shfl_xor_sync(0xffffffffu, cL.sec, m);
                o.idx  = __shfl_xor_sync(0xffffffffu, cL.idx, m);
                mergeBS(cL, o);
                o.best = __shfl_xor_sync(0xffffffffu, cH.best, m);
                o.sec  = __shfl_xor_sync(0xffffffffu, cH.sec, m);
                o.idx  = __shfl_xor_sync(0xffffffffu, cH.idx, m);
                mergeBS(cH, o);
            }
            if ((lane & 3) == 0) {
                int rL = mb * 16 + (lane >> 2), rH = rL + 8;
                keyb[wid * 128 + rL] = ((ull)fenc(cL.best) << 32) | (unsigned)cL.idx;
                secb[wid * 128 + rL] = cL.sec;
                keyb[wid * 128 + rH] = ((ull)fenc(cH.best) << 32) | (unsigned)cH.idx;
                secb[wid * 128 + rH] = cH.sec;
            }
        }
        __syncthreads();

        // ---- cross-warp merge (one thread per row), flags, z, err ----
        const long i0 = (long)tile * TILE_M;
        if (tid < TILE_M) {
            ull bk = keyb[tid];
            float secv = secb[tid];
            #pragma unroll
            for (int w = 1; w < NW; w++) {
                ull k = keyb[w * 128 + tid];
                float sv = secb[w * 128 + tid];
                if (k < bk) { secv = fminf(secv, fdec((unsigned)(bk >> 32))); bk = k; secv = fminf(secv, sv); }
                else        { secv = fminf(secv, fdec((unsigned)(k >> 32))); }
            }
            float d = fdec((unsigned)(bk >> 32));
            int z = (int)(bk & 0xffffffffull);
            zrow[tid] = z;
            out_z[i0 + tid] = (float)z;
            redrow[tid] = fmaxf(vn_s[tid] + d, 0.0f);
            if (secv - d <= TAU) {
                int p = atomicAdd_block(fcnt, 1);
                if (p < FLGMAX) flg[p] = (int)(i0 + tid);
            }
        }
        __syncthreads();

        // ---- gather vecs_hat = codebook[z]; per-tile loss sum ----
        for (int n = tid; n < TILE_M * (KDIM / 4); n += NT) {
            int row = n >> 4, q = n & 15;
            float4 v = __ldg((const float4*)(cb + (long)zrow[row] * KDIM) + q);
            *(float4*)(out + (i0 + row) * KDIM + q * 4) = v;
        }
        if (wid == 0) {
            float s = 0.f;
            #pragma unroll
            for (int j = 0; j < 4; j++) s += redrow[lane * 4 + j];
            #pragma unroll
            for (int o = 16; o > 0; o >>= 1) s += __shfl_down_sync(0xffffffffu, s, o);
            if (lane == 0) g_tilesum[tile] = s;
        }
        tile = tnext;
        buf ^= 1;
        __syncthreads();
    }

    // ---- inline exact cleanup (bit-identical reference rounding) ----
    __syncthreads();
    {
        int cnt = fcnt[0]; if (cnt > FLGMAX) cnt = FLGMAX;
        for (int f = wid; f < cnt; f += NW) {
            const int i = flg[f];
            const float* v = vecs + (long)i * KDIM;
            float vn = 0.f;
            #pragma unroll
            for (int q = 0; q < KDIM / 4; q++) {
                float4 t = __ldg((const float4*)v + q);
                vn = fmaf(t.x, t.x, vn);
                vn = fmaf(t.y, t.y, vn);
                vn = fmaf(t.z, t.z, vn);
                vn = fmaf(t.w, t.w, vn);
            }
            ull bk = ~0ull;
            for (int jj = 0; jj < 16; jj++) {
                int s = lane * 16 + jj;
                const float* c = cb + (long)s * KDIM;
                float ae = 0.f, ao = 0.f;
                #pragma unroll
                for (int kp = 0; kp < KDIM / 2; kp++) {
                    ae = fmaf(v[2 * kp],     c[2 * kp],     ae);
                    ao = fmaf(v[2 * kp + 1], c[2 * kp + 1], ao);
                }
                float dot = __fadd_rn(ae, ao);
                float d = __fadd_rn(__fmaf_rn(-2.0f, dot, vn), cnsm[s]);
                ull key = ((ull)__float_as_uint(d) << 32) | (unsigned)s;
                bk = key < bk ? key : bk;
            }
            #pragma unroll
            for (int o = 16; o > 0; o >>= 1) {
                ull other = __shfl_xor_sync(0xffffffffu, bk, o);
                bk = other < bk ? other : bk;
            }
            int z = (int)(bk & 0xffffffffull);
            if (lane == 0) out_z[i] = (float)z;
            out[(long)i * KDIM + lane]      = __ldg(&cb[(long)z * KDIM + lane]);
            out[(long)i * KDIM + lane + 32] = __ldg(&cb[(long)z * KDIM + lane + 32]);
        }
    }

    // ---- last CTA: fixed-order loss reduction, reset counters ----
    __syncthreads();
    if (tid == 0) __threadfence();
    __syncthreads();
    if (tid < 32) {
        unsigned t = 0xffffffffu;
        if (tid == 0) t = atomicAdd(&g_ticket, 1u);
        t = __shfl_sync(0xffffffffu, t, 0);
        if (t == (unsigned)(nctas - 1)) {
            __threadfence();
            double s = 0.0;
            for (int j = 0; j < 16; j++) {
                int idx = lane * 16 + j;
                if (idx < ntiles) s += (double)__ldcg(&g_tilesum[idx]);
            }
            #pragma unroll
            for (int o = 16; o > 0; o >>= 1) s += __shfl_down_sync(0xffffffffu, s, o);
            if (lane == 0) {
                float mean = (float)(s / (double)N);
                long base = (long)N * KDIM + N;
                out[base]     = mean;   // l_commit
                out[base + 1] = mean;   // l_codebook
                g_ticket = 0;
                g_next = (unsigned)nctas;
            }
        }
    }
}

extern "C" void kernel_launch(void* const* d_in, const int* in_sizes, int n_in,
                              void* d_out, int out_size) {
    const float* vecs = (const float*)d_in[0];
    const float* cb   = (const float*)d_in[1];
    float* out = (float*)d_out;

    int N = in_sizes[0] / KDIM;          // 65536
    int ntiles = N / TILE_M;             // 512
    int nctas = GRID;

    cudaFuncSetAttribute(vq_all, cudaFuncAttributeMaxDynamicSharedMemorySize, SMEM_TOTAL);
    vq_all<<<nctas, NT, SMEM_TOTAL>>>(vecs, cb, out, N, ntiles, nctas);
}